// round 7
// baseline (speedup 1.0000x reference)
#include <cuda_runtime.h>
#include <cuda_bf16.h>
#include <cstdint>
#include <math.h>

#define BDIM   4096
#define INDIM  256
#define OUTDIM 256
#define NC     8
#define KDIM   (INDIM * NC)      // 2048
#define KSPLIT 2
#define KHALF  (KDIM / KSPLIT)   // 1024

// ---------------- scratch (static device globals; no allocations) ----------
// B stored [i][o][c]  (same layout as coefs => coalesced build)
__device__ __nv_bfloat16 g_Bh[(size_t)INDIM * OUTDIM * NC]; // 1 MB
__device__ float g_part[(size_t)KSPLIT * BDIM * OUTDIM];    // 8 MB partials
__device__ float g_rvp[KSPLIT * BDIM];                      // rv partials

// ---------------------------------------------------------------------------
// 1) B[i][o][c] = bf16( spline_scale[i,o] * coefs[i,o,c] )  — pure elementwise
// ---------------------------------------------------------------------------
__global__ __launch_bounds__(256) void build_W_kernel(
    const float* __restrict__ coefs, const float* __restrict__ spline_scale) {
    int idx4 = blockIdx.x * 256 + threadIdx.x;     // float4 group id
    float ss = spline_scale[idx4 >> 1];            // (i,o) = idx4/2
    float4 v = ((const float4*)coefs)[idx4];
    __nv_bfloat162 lo = __floats2bfloat162_rn(ss * v.x, ss * v.y);
    __nv_bfloat162 hi = __floats2bfloat162_rn(ss * v.z, ss * v.w);
    uint2 w;
    w.x = *(uint32_t*)&lo;
    w.y = *(uint32_t*)&hi;
    ((uint2*)g_Bh)[idx4] = w;
}

// ---------------------------------------------------------------------------
// 2) fused GEMM, single-pass bf16, split-K=2
//    CTA 64x64, BK=64, 128 threads (4 warps, warp tile 32x32)
// ---------------------------------------------------------------------------
#define BM 64
#define BN 64
#define BK 64
#define NTS (KHALF / BK)        // 16 k-chunks per split

#define ROWB 144                // 128B data + 16B pad
#define TILE_B (64 * ROWB)      // 9216 per tile
// stage layout: A @0, B @TILE_B
#define STAGE_B (2 * TILE_B)    // 18432
#define GEMM_SMEM (2 * STAGE_B) // 36864

__device__ __forceinline__ uint32_t smem_u32(const void* p) {
    uint32_t a;
    asm("{ .reg .u64 t; cvta.to.shared.u64 t, %1; cvt.u32.u64 %0, t; }"
        : "=r"(a) : "l"(p));
    return a;
}
__device__ __forceinline__ void cp16(uint32_t s, const void* g) {
    asm volatile("cp.async.cg.shared.global [%0], [%1], 16;" :: "r"(s), "l"(g));
}
__device__ __forceinline__ void ldsm_x4(uint32_t* r, uint32_t addr) {
    asm volatile("ldmatrix.sync.aligned.m8n8.x4.shared.b16 {%0,%1,%2,%3}, [%4];"
                 : "=r"(r[0]), "=r"(r[1]), "=r"(r[2]), "=r"(r[3]) : "r"(addr));
}
__device__ __forceinline__ void mma_bf16(float* d, const uint32_t* a, const uint32_t* b) {
    asm volatile(
        "mma.sync.aligned.m16n8k16.row.col.f32.bf16.bf16.f32 "
        "{%0,%1,%2,%3}, {%4,%5,%6,%7}, {%8,%9}, {%0,%1,%2,%3};"
        : "+f"(d[0]), "+f"(d[1]), "+f"(d[2]), "+f"(d[3])
        : "r"(a[0]), "r"(a[1]), "r"(a[2]), "r"(a[3]), "r"(b[0]), "r"(b[1]));
}

// B prefetch from [i][o][c] layout: chunk (c = i-sub 0..7, r = o-sub 0..63)
// lanes ordered r-fastest => 32 consecutive 16B chunks = 512B contiguous
__device__ __forceinline__ void prefetch_B(uint32_t sbase, int i0, int n0, int tid) {
#pragma unroll
    for (int p = 0; p < 4; ++p) {
        int idx = p * 128 + tid;           // 0..511
        int c = idx >> 6, r = idx & 63;
        cp16(sbase + TILE_B + r * ROWB + c * 16,
             g_Bh + ((size_t)(i0 + c) * OUTDIM + n0 + r) * NC);
    }
    asm volatile("cp.async.commit_group;" ::: "memory");
}

// A math+store from preloaded x values (no global loads here)
__device__ __forceinline__ void compute_A(
    char* abase, const float* xv, float rs, float* rv_acc,
    float alpha, const float* r1, const float* r2, int tid) {
#pragma unroll
    for (int p = 0; p < 4; ++p) {
        int b = p * 16 + (tid >> 3);
        float t = tanhf(xv[p]);
        rv_acc[p] += rs * t;

        float pr[NC];
        pr[0] = 1.0f;
        pr[1] = (alpha + 1.0f) + (alpha + alpha + 2.0f) * (t - 1.0f) * 0.5f;
#pragma unroll
        for (int n = 2; n < NC; n++)
            pr[n] = r1[n] * t * pr[n - 1] - r2[n] * pr[n - 2];

        uint4 uh;
        uint32_t* ph = (uint32_t*)&uh;
#pragma unroll
        for (int c = 0; c < 4; c++) {
            __nv_bfloat162 t2 = __floats2bfloat162_rn(pr[2 * c], pr[2 * c + 1]);
            ph[c] = *(uint32_t*)&t2;
        }
        *(uint4*)(abase + b * ROWB + (tid & 7) * 16) = uh;
    }
}

__global__ __launch_bounds__(128, 6) void gemm_fused(
    const float* __restrict__ x, const float* __restrict__ resid_scale,
    const float* __restrict__ aat) {
    extern __shared__ char smem[];
    const int tid  = threadIdx.x;
    const int wid  = tid >> 5;
    const int lane = tid & 31;
    const int m0   = blockIdx.x * BM;
    const int n0   = blockIdx.y * BN;
    const int z    = blockIdx.z;
    const int mbase = (wid & 1) * 32;
    const int nbase = (wid >> 1) * 32;
    const uint32_t sb = smem_u32(smem);

    // recurrence coefficients computed locally
    const float alpha = tanhf(__ldg(aat));
    float r1[NC], r2[NC];
#pragma unroll
    for (int n = 2; n < NC; n++) {
        float c = 2.0f * n + 2.0f * alpha;
        float A = 2.0f * n * (n + 2.0f * alpha) * (c - 2.0f);
        r1[n] = (c - 1.0f) * c * (c - 2.0f) / A;
        r2[n] = 2.0f * (n + alpha - 1.0f) * (n + alpha - 1.0f) * c / A;
    }

    float acc[2][4][4];
#pragma unroll
    for (int i = 0; i < 2; i++)
#pragma unroll
        for (int j = 0; j < 4; j++)
#pragma unroll
            for (int r = 0; r < 4; r++) acc[i][j][r] = 0.0f;
    float rv_acc[4] = {0.f, 0.f, 0.f, 0.f};

    // ldmatrix per-lane address pieces (mapping verified R3-R6)
    const int g  = lane >> 3;
    const int lr = lane & 7;
    const int a_row_off = lr + ((g & 1) ? 8 : 0);
    const int kb_off    = (g >= 2) ? 16 : 0;

    const int ibase = z * (KHALF / NC);   // i-range of this split
    const int il    = tid & 7;
    const int brow  = tid >> 3;
    const float* xcol = x + (size_t)m0 * INDIM;   // x[m0..m0+63][*]

    // prologue: x for stage 0, A(0), B(0), B(1)
    float xv[4], rs;
    {
        int i = ibase + il;
        rs = resid_scale[i];
#pragma unroll
        for (int p = 0; p < 4; ++p)
            xv[p] = xcol[(size_t)(p * 16 + brow) * INDIM + i];
    }
    compute_A(smem, xv, rs, rv_acc, alpha, r1, r2, tid);
    prefetch_B(sb, ibase, n0, tid);
    prefetch_B(sb + STAGE_B, ibase + 8, n0, tid);
    asm volatile("cp.async.wait_group 1;" ::: "memory");
    __syncthreads();

    for (int kt = 0; kt < NTS; ++kt) {
        const int s = kt & 1;
        const uint32_t st = sb + s * STAGE_B;

        // issue x loads for stage kt+1 BEFORE the MMA phase (latency hides
        // under tensor work); consumed after the next barrier.
        if (kt + 1 < NTS) {
            int i = ibase + (kt + 1) * 8 + il;
#pragma unroll
            for (int p = 0; p < 4; ++p)
                xv[p] = xcol[(size_t)(p * 16 + brow) * INDIM + i];
        }

#pragma unroll
        for (int ks = 0; ks < 4; ++ks) {
            uint32_t a[2][4], b[4][2];
#pragma unroll
            for (int mf = 0; mf < 2; ++mf) {
                uint32_t row = mbase + mf * 16 + a_row_off;
                ldsm_x4(a[mf], st + row * ROWB + ks * 32 + kb_off);
            }
#pragma unroll
            for (int np = 0; np < 2; ++np) {
                uint32_t row = nbase + np * 16 + lr + ((g >= 2) ? 8 : 0);
                uint32_t kb2 = ks * 32 + ((g & 1) ? 16 : 0);
                uint32_t r4[4];
                ldsm_x4(r4, st + TILE_B + row * ROWB + kb2);
                b[2 * np][0] = r4[0];     b[2 * np][1] = r4[1];
                b[2 * np + 1][0] = r4[2]; b[2 * np + 1][1] = r4[3];
            }
#pragma unroll
            for (int mf = 0; mf < 2; ++mf)
#pragma unroll
                for (int nf = 0; nf < 4; ++nf)
                    mma_bf16(acc[mf][nf], a[mf], b[nf]);
        }
        __syncthreads();   // all warps done reading stage s

        if (kt + 1 < NTS) {
            int i = ibase + (kt + 1) * 8 + il;
            rs = resid_scale[i];
            compute_A(smem + (s ^ 1) * STAGE_B, xv, rs, rv_acc,
                      alpha, r1, r2, tid);
            if (kt + 2 < NTS) {
                prefetch_B(st, ibase + (kt + 2) * 8, n0, tid);
                asm volatile("cp.async.wait_group 1;" ::: "memory");
            } else {
                asm volatile("cp.async.wait_group 0;" ::: "memory");
            }
            __syncthreads();
        }
    }

    // rv partial: reduce 8 lanes (same b); all warps store disjoint slots
    if (blockIdx.y == 0) {
#pragma unroll
        for (int p = 0; p < 4; ++p) {
            float v = rv_acc[p];
            v += __shfl_xor_sync(0xffffffffu, v, 1);
            v += __shfl_xor_sync(0xffffffffu, v, 2);
            v += __shfl_xor_sync(0xffffffffu, v, 4);
            if ((lane & 7) == 0)
                g_rvp[z * BDIM + m0 + p * 16 + brow] = v;
        }
    }

    // write partial tile
    float* dst = g_part + (size_t)z * BDIM * OUTDIM;
    const int l4 = lane >> 2, l2 = (lane & 3) * 2;
#pragma unroll
    for (int mf = 0; mf < 2; ++mf) {
        int m = m0 + mbase + mf * 16 + l4;
#pragma unroll
        for (int nf = 0; nf < 4; ++nf) {
            int n = n0 + nbase + nf * 8 + l2;
            *(float2*)&dst[(size_t)m * OUTDIM + n] =
                make_float2(acc[mf][nf][0], acc[mf][nf][1]);
            *(float2*)&dst[(size_t)(m + 8) * OUTDIM + n] =
                make_float2(acc[mf][nf][2], acc[mf][nf][3]);
        }
    }
}

// ---------------------------------------------------------------------------
// 3) combine: out = (part0 + part1 + rv0 + rv1) / IN
// ---------------------------------------------------------------------------
__global__ __launch_bounds__(256) void combine_kernel(float* __restrict__ out) {
    int idx = blockIdx.x * 256 + threadIdx.x;   // float4 index
    int m = idx >> 6, c4 = (idx & 63) * 4;
    size_t o0 = (size_t)m * OUTDIM + c4;
    float4 a = *(float4*)&g_part[o0];
    float4 b = *(float4*)&g_part[(size_t)BDIM * OUTDIM + o0];
    float rv = g_rvp[m] + g_rvp[BDIM + m];
    const float s = 1.0f / (float)INDIM;
    float4 o;
    o.x = (a.x + b.x + rv) * s;
    o.y = (a.y + b.y + rv) * s;
    o.z = (a.z + b.z + rv) * s;
    o.w = (a.w + b.w + rv) * s;
    *(float4*)&out[o0] = o;
}

// ---------------------------------------------------------------------------
extern "C" void kernel_launch(void* const* d_in, const int* in_sizes, int n_in,
                              void* d_out, int out_size) {
    const float *x = nullptr, *coefs = nullptr, *aat = nullptr;
    const float *resid_scale = nullptr, *spline_scale = nullptr;
    for (int i = 0; i < n_in; i++) {
        switch (in_sizes[i]) {
            case BDIM * INDIM:        x            = (const float*)d_in[i]; break;
            case INDIM * OUTDIM * NC: coefs        = (const float*)d_in[i]; break;
            case 1:                   aat          = (const float*)d_in[i]; break;
            case INDIM:               resid_scale  = (const float*)d_in[i]; break;
            case INDIM * OUTDIM:      spline_scale = (const float*)d_in[i]; break;
            default: break;
        }
    }
    float* out = (float*)d_out;

    cudaFuncSetAttribute(gemm_fused, cudaFuncAttributeMaxDynamicSharedMemorySize, GEMM_SMEM);

    build_W_kernel<<<(INDIM * OUTDIM * NC / 4) / 256, 256>>>(coefs, spline_scale);
    dim3 grid(BDIM / BM, OUTDIM / BN, KSPLIT);
    gemm_fused<<<grid, 128, GEMM_SMEM>>>(x, resid_scale, aat);
    combine_kernel<<<(BDIM * OUTDIM / 4) / 256, 256>>>(out);
}